// round 15
// baseline (speedup 1.0000x reference)
#include <cuda_runtime.h>
#include <cuda_fp16.h>

#define NN      50000
#define FDIM    256
#define H1DIM   128
#define NHEADS  8
#define CDIM2   16
#define CAP     96               // max real in-degree bucket capacity (Poisson(16) tail: safe)

// ---- scratch (__device__ globals; no allocation allowed) -------------------
__device__ float g_hp1[NN * H1DIM];
__device__ float g_as1[NN * NHEADS];
__device__ float g_ad1[NN * NHEADS];
__device__ float g_h1[NN * H1DIM];
__device__ float g_h2[NN * CDIM2];
__device__ float g_as2[NN];
__device__ float g_ad2[NN];
__device__ int g_deg[NN];              // zero-init; re-zeroed by agg2 tail each launch
__device__ int g_eidx[NN * CAP];       // bucketed incoming-edge src lists (real edges only)

// ---------------------------------------------------------------------------
// scatter: single-pass bucket build, REAL edges only (self-loops implicit in agg).
// Flat 8-edge unroll for atomic MLP; scalar tail path for the last partial oct.
// ---------------------------------------------------------------------------
__global__ void scatter_kernel(const int* __restrict__ ei, int E) {
    int octs = (E + 7) >> 3;
    int idx = blockIdx.x * blockDim.x + threadIdx.x;
    if (idx >= octs) return;
    int base = idx * 8;
    if (base + 8 <= E) {
        int s0 = ei[base + 0], s1 = ei[base + 1], s2 = ei[base + 2], s3 = ei[base + 3];
        int s4 = ei[base + 4], s5 = ei[base + 5], s6 = ei[base + 6], s7 = ei[base + 7];
        int d0 = ei[E + base + 0], d1 = ei[E + base + 1], d2 = ei[E + base + 2], d3 = ei[E + base + 3];
        int d4 = ei[E + base + 4], d5 = ei[E + base + 5], d6 = ei[E + base + 6], d7 = ei[E + base + 7];
        int p0 = atomicAdd(&g_deg[d0], 1);
        int p1 = atomicAdd(&g_deg[d1], 1);
        int p2 = atomicAdd(&g_deg[d2], 1);
        int p3 = atomicAdd(&g_deg[d3], 1);
        int p4 = atomicAdd(&g_deg[d4], 1);
        int p5 = atomicAdd(&g_deg[d5], 1);
        int p6 = atomicAdd(&g_deg[d6], 1);
        int p7 = atomicAdd(&g_deg[d7], 1);
        g_eidx[d0 * CAP + p0] = s0;
        g_eidx[d1 * CAP + p1] = s1;
        g_eidx[d2 * CAP + p2] = s2;
        g_eidx[d3 * CAP + p3] = s3;
        g_eidx[d4 * CAP + p4] = s4;
        g_eidx[d5 * CAP + p5] = s5;
        g_eidx[d6 * CAP + p6] = s6;
        g_eidx[d7 * CAP + p7] = s7;
    } else {
        for (int e = base; e < E; e++) {
            int s = ei[e], d = ei[E + e];
            int p = atomicAdd(&g_deg[d], 1);
            g_eidx[d * CAP + p] = s;
        }
    }
}

// ---------------------------------------------------------------------------
// GEMM1 (fp16 MMA, fp32 accum + fused alpha epilogue):
//   g_hp1[N,128] = x[N,256] @ W1[256,128]   (fp32 output)
//   g_as1/g_ad1  = per-node attention logits (from fp16-staged tile)
// 128x128 tile, 8 warps in 4(m)x2(n); each warp 32x64 via m16n8k16.
// ---------------------------------------------------------------------------
__global__ void __launch_bounds__(256) gemm1_kernel(const float* __restrict__ X,
                                                    const float* __restrict__ W,
                                                    const float* __restrict__ att_src,
                                                    const float* __restrict__ att_dst) {
    union SmemU {
        struct { __half A[128][40]; __half B[128][40]; } ld;   // MMA tiles
        __half stage[128][136];                                 // epilogue staging
    };
    __shared__ __align__(16) SmemU su;
    const int tid = threadIdx.x;
    const int warp = tid >> 5, lane = tid & 31;
    const int wm = warp >> 1, wn = warp & 1;
    const int row0 = blockIdx.x * 128;
    const int gid = lane >> 2, qid = lane & 3;

    float acc[2][8][4];
#pragma unroll
    for (int mt = 0; mt < 2; mt++)
#pragma unroll
        for (int nt = 0; nt < 8; nt++)
#pragma unroll
            for (int j = 0; j < 4; j++) acc[mt][nt][j] = 0.f;

    for (int k0 = 0; k0 < FDIM; k0 += 32) {
        // A tile: 128x32 -> fp16
#pragma unroll
        for (int t = 0; t < 4; t++) {
            int i = tid + t * 256;
            int r = i >> 3, c = (i & 7) << 2;
            float4 v = make_float4(0.f, 0.f, 0.f, 0.f);
            if (row0 + r < NN) v = *(const float4*)(X + (size_t)(row0 + r) * FDIM + k0 + c);
            *(__half2*)&su.ld.A[r][c]     = __floats2half2_rn(v.x, v.y);
            *(__half2*)&su.ld.A[r][c + 2] = __floats2half2_rn(v.z, v.w);
        }
        // B tile: 32(k)x128(n), stored transposed [n][k] as fp16
#pragma unroll
        for (int t = 0; t < 4; t++) {
            int i = tid + t * 256;
            int r = i & 31;             // k within chunk
            int c = (i >> 5) << 2;      // n
            float4 v = *(const float4*)(W + (size_t)(k0 + r) * H1DIM + c);
            su.ld.B[c + 0][r] = __float2half_rn(v.x);
            su.ld.B[c + 1][r] = __float2half_rn(v.y);
            su.ld.B[c + 2][r] = __float2half_rn(v.z);
            su.ld.B[c + 3][r] = __float2half_rn(v.w);
        }
        __syncthreads();
#pragma unroll
        for (int kk = 0; kk < 2; kk++) {
            const int ks = kk * 16;
            unsigned a[2][4], b[8][2];
#pragma unroll
            for (int mt = 0; mt < 2; mt++) {
                int rw = wm * 32 + mt * 16 + gid;
                a[mt][0] = *(const unsigned*)&su.ld.A[rw][ks + qid * 2];
                a[mt][1] = *(const unsigned*)&su.ld.A[rw + 8][ks + qid * 2];
                a[mt][2] = *(const unsigned*)&su.ld.A[rw][ks + 8 + qid * 2];
                a[mt][3] = *(const unsigned*)&su.ld.A[rw + 8][ks + 8 + qid * 2];
            }
#pragma unroll
            for (int nt = 0; nt < 8; nt++) {
                int cl = wn * 64 + nt * 8 + gid;
                b[nt][0] = *(const unsigned*)&su.ld.B[cl][ks + qid * 2];
                b[nt][1] = *(const unsigned*)&su.ld.B[cl][ks + 8 + qid * 2];
            }
#pragma unroll
            for (int mt = 0; mt < 2; mt++)
#pragma unroll
                for (int nt = 0; nt < 8; nt++) {
                    asm volatile(
                        "mma.sync.aligned.m16n8k16.row.col.f32.f16.f16.f32 "
                        "{%0,%1,%2,%3}, {%4,%5,%6,%7}, {%8,%9}, {%0,%1,%2,%3};\n"
                        : "+f"(acc[mt][nt][0]), "+f"(acc[mt][nt][1]),
                          "+f"(acc[mt][nt][2]), "+f"(acc[mt][nt][3])
                        : "r"(a[mt][0]), "r"(a[mt][1]), "r"(a[mt][2]), "r"(a[mt][3]),
                          "r"(b[nt][0]), "r"(b[nt][1]));
                }
        }
        __syncthreads();
    }
    // epilogue: store fp32 h to gmem + fp16 tile to smem stage
#pragma unroll
    for (int mt = 0; mt < 2; mt++) {
        int r0 = wm * 32 + mt * 16 + gid;
        int grw = row0 + r0;
#pragma unroll
        for (int nt = 0; nt < 8; nt++) {
            int cl = wn * 64 + nt * 8 + qid * 2;
            *(__half2*)&su.stage[r0][cl]     = __floats2half2_rn(acc[mt][nt][0], acc[mt][nt][1]);
            *(__half2*)&su.stage[r0 + 8][cl] = __floats2half2_rn(acc[mt][nt][2], acc[mt][nt][3]);
            if (grw < NN)
                *(float2*)(g_hp1 + (size_t)grw * H1DIM + cl) =
                    make_float2(acc[mt][nt][0], acc[mt][nt][1]);
            if (grw + 8 < NN)
                *(float2*)(g_hp1 + (size_t)(grw + 8) * H1DIM + cl) =
                    make_float2(acc[mt][nt][2], acc[mt][nt][3]);
        }
    }
    __syncthreads();
    // alpha epilogue: each warp computes logits for 16 rows of the tile
    {
        int head = lane >> 2, sub = lane & 3;
        float4 A4 = *(const float4*)(att_src + head * 16 + sub * 4);
        float4 D4 = *(const float4*)(att_dst + head * 16 + sub * 4);
#pragma unroll
        for (int rr = 0; rr < 16; rr++) {
            int r = warp * 16 + rr;
            int grow = row0 + r;
            if (grow >= NN) break;
            float2 f01 = __half22float2(*(__half2*)&su.stage[r][lane * 4]);
            float2 f23 = __half22float2(*(__half2*)&su.stage[r][lane * 4 + 2]);
            float s = f01.x * A4.x + f01.y * A4.y + f23.x * A4.z + f23.y * A4.w;
            float d = f01.x * D4.x + f01.y * D4.y + f23.x * D4.z + f23.y * D4.w;
            s += __shfl_xor_sync(0xffffffffu, s, 1);
            s += __shfl_xor_sync(0xffffffffu, s, 2);
            d += __shfl_xor_sync(0xffffffffu, d, 1);
            d += __shfl_xor_sync(0xffffffffu, d, 2);
            if (sub == 0) { g_as1[grow * 8 + head] = s; g_ad1[grow * 8 + head] = d; }
        }
    }
}

// ---------------------------------------------------------------------------
// agg1: bucket gather + implicit self-loop + softmax-normalize + bias + ELU.
// One warp per dst node; int4 eidx loads.
// ---------------------------------------------------------------------------
__device__ __forceinline__ float edge_w1(int s, int head, float myad) {
    float t = __ldg(g_as1 + s * 8 + head) + myad;
    t = t > 0.f ? t : 0.2f * t;
    return __expf(t);
}

__global__ void __launch_bounds__(256) agg1_kernel(const float* __restrict__ b1) {
    int gw = (blockIdx.x * blockDim.x + threadIdx.x) >> 5;
    int lane = threadIdx.x & 31;
    if (gw >= NN) return;
    int head = lane >> 2;
    int deg = g_deg[gw];
    int beg = gw * CAP;
    float myad = g_ad1[gw * 8 + head];
    // self-loop contribution (implicit)
    float wself = edge_w1(gw, head, myad);
    float4 hs = *(const float4*)(g_hp1 + (size_t)gw * H1DIM + lane * 4);
    float den = wself;
    float a0 = wself * hs.x, a1 = wself * hs.y, a2 = wself * hs.z, a3 = wself * hs.w;
    int p = 0;
    for (; p + 4 <= deg; p += 4) {
        int4 s4 = *(const int4*)(g_eidx + beg + p);
        float w0 = edge_w1(s4.x, head, myad);
        float w1 = edge_w1(s4.y, head, myad);
        float w2 = edge_w1(s4.z, head, myad);
        float w3 = edge_w1(s4.w, head, myad);
        float4 h0 = *(const float4*)(g_hp1 + (size_t)s4.x * H1DIM + lane * 4);
        float4 h1 = *(const float4*)(g_hp1 + (size_t)s4.y * H1DIM + lane * 4);
        float4 h2 = *(const float4*)(g_hp1 + (size_t)s4.z * H1DIM + lane * 4);
        float4 h3 = *(const float4*)(g_hp1 + (size_t)s4.w * H1DIM + lane * 4);
        den += (w0 + w1) + (w2 + w3);
        a0 += w0 * h0.x + w1 * h1.x + w2 * h2.x + w3 * h3.x;
        a1 += w0 * h0.y + w1 * h1.y + w2 * h2.y + w3 * h3.y;
        a2 += w0 * h0.z + w1 * h1.z + w2 * h2.z + w3 * h3.z;
        a3 += w0 * h0.w + w1 * h1.w + w2 * h2.w + w3 * h3.w;
    }
    for (; p < deg; p++) {
        int s = g_eidx[beg + p];
        float w = edge_w1(s, head, myad);
        float4 h = *(const float4*)(g_hp1 + (size_t)s * H1DIM + lane * 4);
        den += w;
        a0 += w * h.x; a1 += w * h.y; a2 += w * h.z; a3 += w * h.w;
    }
    float inv = __frcp_rn(den);
    const float* bb = b1 + lane * 4;
    float v0 = a0 * inv + bb[0];
    float v1 = a1 * inv + bb[1];
    float v2 = a2 * inv + bb[2];
    float v3 = a3 * inv + bb[3];
    v0 = v0 > 0.f ? v0 : __expf(v0) - 1.f;
    v1 = v1 > 0.f ? v1 : __expf(v1) - 1.f;
    v2 = v2 > 0.f ? v2 : __expf(v2) - 1.f;
    v3 = v3 > 0.f ? v3 : __expf(v3) - 1.f;
    *(float4*)(g_h1 + (size_t)gw * H1DIM + lane * 4) = make_float4(v0, v1, v2, v3);
}

// ---------------------------------------------------------------------------
// GEMM2 (fp16 MMA) + alpha2 fused: h2[N,16] = h1[N,128] @ W2[128,16].
// 128-row tile per block, 8 warps x 16 rows; 2 n8-tiles; k=128 in 8 MMAs.
// alpha2 logits computed from fp32 accumulators in the epilogue.
// ---------------------------------------------------------------------------
__global__ void __launch_bounds__(256) gemm2_kernel(const float* __restrict__ W2,
                             const float* __restrict__ as2w, const float* __restrict__ ad2w) {
    __shared__ __align__(16) __half Hs[128][136];
    __shared__ __align__(16) __half Bt[16][136];
    const int tid = threadIdx.x;
    const int warp = tid >> 5, lane = tid & 31;
    const int gid = lane >> 2, qid = lane & 3;
    const int row0 = blockIdx.x * 128;

    // W2 -> Bt[n][k] fp16 (2048 elems, 8/thread)
#pragma unroll
    for (int t = 0; t < 8; t++) {
        int i = tid + t * 256;
        int k = i >> 4, c = i & 15;
        Bt[c][k] = __float2half_rn(W2[i]);
    }
    // h1 tile -> Hs fp16 (128 rows x 128, 16 float4 per thread)
#pragma unroll
    for (int t = 0; t < 16; t++) {
        int i = tid + t * 256;
        int r = i >> 5, c = (i & 31) << 2;
        float4 v = make_float4(0.f, 0.f, 0.f, 0.f);
        if (row0 + r < NN) v = *(const float4*)(g_h1 + (size_t)(row0 + r) * H1DIM + c);
        *(__half2*)&Hs[r][c]     = __floats2half2_rn(v.x, v.y);
        *(__half2*)&Hs[r][c + 2] = __floats2half2_rn(v.z, v.w);
    }
    __syncthreads();

    const int base = warp * 16;
    float acc[2][4];
#pragma unroll
    for (int nt = 0; nt < 2; nt++)
#pragma unroll
        for (int j = 0; j < 4; j++) acc[nt][j] = 0.f;

#pragma unroll
    for (int ks = 0; ks < H1DIM; ks += 16) {
        unsigned a[4], b[2][2];
        a[0] = *(const unsigned*)&Hs[base + gid][ks + qid * 2];
        a[1] = *(const unsigned*)&Hs[base + 8 + gid][ks + qid * 2];
        a[2] = *(const unsigned*)&Hs[base + gid][ks + 8 + qid * 2];
        a[3] = *(const unsigned*)&Hs[base + 8 + gid][ks + 8 + qid * 2];
#pragma unroll
        for (int nt = 0; nt < 2; nt++) {
            b[nt][0] = *(const unsigned*)&Bt[nt * 8 + gid][ks + qid * 2];
            b[nt][1] = *(const unsigned*)&Bt[nt * 8 + gid][ks + 8 + qid * 2];
        }
#pragma unroll
        for (int nt = 0; nt < 2; nt++) {
            asm volatile(
                "mma.sync.aligned.m16n8k16.row.col.f32.f16.f16.f32 "
                "{%0,%1,%2,%3}, {%4,%5,%6,%7}, {%8,%9}, {%0,%1,%2,%3};\n"
                : "+f"(acc[nt][0]), "+f"(acc[nt][1]), "+f"(acc[nt][2]), "+f"(acc[nt][3])
                : "r"(a[0]), "r"(a[1]), "r"(a[2]), "r"(a[3]),
                  "r"(b[nt][0]), "r"(b[nt][1]));
        }
    }
    // epilogue: rows r1 = row0+base+gid (c0,c1) and r2 = r1+8 (c2,c3)
    int r1 = row0 + base + gid, r2 = r1 + 8;
#pragma unroll
    for (int nt = 0; nt < 2; nt++) {
        int cl = nt * 8 + qid * 2;
        if (r1 < NN) *(float2*)(g_h2 + (size_t)r1 * CDIM2 + cl) = make_float2(acc[nt][0], acc[nt][1]);
        if (r2 < NN) *(float2*)(g_h2 + (size_t)r2 * CDIM2 + cl) = make_float2(acc[nt][2], acc[nt][3]);
    }
    // alpha2 logits: reduce over the 4 qid lanes holding each row's 16 cols
    float as_a = __ldg(as2w + qid * 2), as_b = __ldg(as2w + qid * 2 + 1);
    float as_c = __ldg(as2w + 8 + qid * 2), as_d = __ldg(as2w + 8 + qid * 2 + 1);
    float ad_a = __ldg(ad2w + qid * 2), ad_b = __ldg(ad2w + qid * 2 + 1);
    float ad_c = __ldg(ad2w + 8 + qid * 2), ad_d = __ldg(ad2w + 8 + qid * 2 + 1);
    float sv1 = acc[0][0] * as_a + acc[0][1] * as_b + acc[1][0] * as_c + acc[1][1] * as_d;
    float dv1 = acc[0][0] * ad_a + acc[0][1] * ad_b + acc[1][0] * ad_c + acc[1][1] * ad_d;
    float sv2 = acc[0][2] * as_a + acc[0][3] * as_b + acc[1][2] * as_c + acc[1][3] * as_d;
    float dv2 = acc[0][2] * ad_a + acc[0][3] * ad_b + acc[1][2] * ad_c + acc[1][3] * ad_d;
#pragma unroll
    for (int off = 1; off <= 2; off <<= 1) {
        sv1 += __shfl_xor_sync(0xffffffffu, sv1, off);
        dv1 += __shfl_xor_sync(0xffffffffu, dv1, off);
        sv2 += __shfl_xor_sync(0xffffffffu, sv2, off);
        dv2 += __shfl_xor_sync(0xffffffffu, dv2, off);
    }
    if (qid == 0) {
        if (r1 < NN) { g_as2[r1] = sv1; g_ad2[r1] = dv1; }
        if (r2 < NN) { g_as2[r2] = sv2; g_ad2[r2] = dv2; }
    }
}

// ---------------------------------------------------------------------------
// agg2: one warp per dst node; EIGHT 4-lane groups (8 edges in flight) +
// implicit self-loop (added once, in group 0). Butterfly-reduce across groups.
// Tail: re-zero g_deg for the next replay.
// ---------------------------------------------------------------------------
__global__ void __launch_bounds__(256) agg2_kernel(const float* __restrict__ b2,
                                                   float* __restrict__ out) {
    int gw = (blockIdx.x * blockDim.x + threadIdx.x) >> 5;
    int lane = threadIdx.x & 31;
    if (gw >= NN) return;
    int deg = g_deg[gw];
    int beg = gw * CAP;
    int grp = lane >> 2, sub = lane & 3;
    float ad = g_ad2[gw];
    float4 acc = make_float4(0.f, 0.f, 0.f, 0.f);
    float den = 0.f;
    if (grp == 0) {   // self-loop contribution, once
        float t = __ldg(g_as2 + gw) + ad;
        t = t > 0.f ? t : 0.2f * t;
        float w = __expf(t);
        den = w;
        float4 h = *(const float4*)(g_h2 + (size_t)gw * CDIM2 + sub * 4);
        acc.x = w * h.x; acc.y = w * h.y; acc.z = w * h.z; acc.w = w * h.w;
    }
    for (int p = grp; p < deg; p += 8) {
        int s = g_eidx[beg + p];
        float t = __ldg(g_as2 + s) + ad;
        t = t > 0.f ? t : 0.2f * t;
        float w = __expf(t);
        den += w;
        float4 h = *(const float4*)(g_h2 + (size_t)s * CDIM2 + sub * 4);
        acc.x += w * h.x; acc.y += w * h.y; acc.z += w * h.z; acc.w += w * h.w;
    }
#pragma unroll
    for (int off = 4; off <= 16; off <<= 1) {
        acc.x += __shfl_xor_sync(0xffffffffu, acc.x, off);
        acc.y += __shfl_xor_sync(0xffffffffu, acc.y, off);
        acc.z += __shfl_xor_sync(0xffffffffu, acc.z, off);
        acc.w += __shfl_xor_sync(0xffffffffu, acc.w, off);
        den   += __shfl_xor_sync(0xffffffffu, den, off);
    }
    if (lane < 4) {
        float inv = __frcp_rn(den);
        const float* bb = b2 + lane * 4;
        float4 r;
        r.x = acc.x * inv + bb[0];
        r.y = acc.y * inv + bb[1];
        r.z = acc.z * inv + bb[2];
        r.w = acc.w * inv + bb[3];
        *(float4*)(out + (size_t)gw * CDIM2 + lane * 4) = r;
    }
    if (lane == 0) g_deg[gw] = 0;   // reset for next graph replay
}

// ---------------------------------------------------------------------------
extern "C" void kernel_launch(void* const* d_in, const int* in_sizes, int n_in,
                              void* d_out, int out_size) {
    const float* x   = (const float*)d_in[0];
    const int*   ei  = (const int*)d_in[1];
    const float* W1  = (const float*)d_in[2];
    const float* as1 = (const float*)d_in[3];
    const float* ad1 = (const float*)d_in[4];
    const float* b1  = (const float*)d_in[5];
    const float* W2  = (const float*)d_in[6];
    const float* as2 = (const float*)d_in[7];
    const float* ad2 = (const float*)d_in[8];
    const float* b2  = (const float*)d_in[9];
    const int E = in_sizes[1] / 2;
    const int octs = (E + 7) >> 3;

    scatter_kernel<<<(octs + 255) / 256, 256>>>(ei, E);
    gemm1_kernel<<<(NN + 127) / 128, 256>>>(x, W1, as1, ad1);
    agg1_kernel<<<(NN * 32 + 255) / 256, 256>>>(b1);
    gemm2_kernel<<<(NN + 127) / 128, 256>>>(W2, as2, ad2);
    agg2_kernel<<<(NN * 32 + 255) / 256, 256>>>(b2, (float*)d_out);
}

// round 16
// speedup vs baseline: 1.1943x; 1.1943x over previous
#include <cuda_runtime.h>
#include <cuda_fp16.h>

#define NN      50000
#define FDIM    256
#define H1DIM   128
#define NHEADS  8
#define CDIM2   16
#define CAP     96               // max in-degree bucket capacity (Poisson(16) tail: safe)
#define G1BLOCKS 391             // (NN + 127) / 128 gemm1 tiles

// ---- scratch (__device__ globals; no allocation allowed) -------------------
__device__ float g_hp1[NN * H1DIM];
__device__ float g_as1[NN * NHEADS];
__device__ float g_ad1[NN * NHEADS];
__device__ float g_h1[NN * H1DIM];
__device__ float g_h2[NN * CDIM2];
__device__ float g_as2[NN];
__device__ float g_ad2[NN];
__device__ int g_deg[NN];              // zero-init; re-zeroed by agg2 tail each launch
__device__ int g_eidx[NN * CAP];       // bucketed incoming-edge src lists

// ---------------------------------------------------------------------------
// phase1: fused scatter + GEMM1(fp16 MMA)+alpha1.
// Blocks [0, G1BLOCKS) run the GEMM role; the rest run the scatter role.
// The two roles touch disjoint data (scatter: ei/deg/eidx; gemm: X/W1/hp1/as1/ad1),
// so they overlap freely; the kernel boundary orders both before agg1.
// ---------------------------------------------------------------------------
__global__ void __launch_bounds__(256) phase1_kernel(const float* __restrict__ X,
                                                     const float* __restrict__ W,
                                                     const float* __restrict__ att_src,
                                                     const float* __restrict__ att_dst,
                                                     const int* __restrict__ ei, int E) {
    union SmemU {
        struct { __half A[128][40]; __half B[128][40]; } ld;   // MMA tiles
        __half stage[128][136];                                 // epilogue staging
    };
    __shared__ __align__(16) SmemU su;
    const int tid = threadIdx.x;

    if (blockIdx.x >= G1BLOCKS) {
        // ---- scatter role: 4 real edges per thread + self-loop range ----
        int quads = (E + 3) >> 2;
        int idx = (blockIdx.x - G1BLOCKS) * 256 + tid;
        if (idx < quads) {
            int e0 = idx * 4;
            int n = min(4, E - e0);
            int s0, s1, s2, s3, d0, d1, d2, d3;
            s0 = ei[e0];     d0 = ei[E + e0];
            if (n > 1) { s1 = ei[e0 + 1]; d1 = ei[E + e0 + 1]; }
            if (n > 2) { s2 = ei[e0 + 2]; d2 = ei[E + e0 + 2]; }
            if (n > 3) { s3 = ei[e0 + 3]; d3 = ei[E + e0 + 3]; }
            int p0 = atomicAdd(&g_deg[d0], 1);
            int p1 = (n > 1) ? atomicAdd(&g_deg[d1], 1) : 0;
            int p2 = (n > 2) ? atomicAdd(&g_deg[d2], 1) : 0;
            int p3 = (n > 3) ? atomicAdd(&g_deg[d3], 1) : 0;
            g_eidx[d0 * CAP + p0] = s0;
            if (n > 1) g_eidx[d1 * CAP + p1] = s1;
            if (n > 2) g_eidx[d2 * CAP + p2] = s2;
            if (n > 3) g_eidx[d3 * CAP + p3] = s3;
        } else if (idx < quads + NN) {
            int nd = idx - quads;
            int p = atomicAdd(&g_deg[nd], 1);
            g_eidx[nd * CAP + p] = nd;     // self-loop
        }
        return;
    }

    // ---- GEMM1 role (identical to R14 gemm1_kernel) ----
    const int warp = tid >> 5, lane = tid & 31;
    const int wm = warp >> 1, wn = warp & 1;
    const int row0 = blockIdx.x * 128;
    const int gid = lane >> 2, qid = lane & 3;

    float acc[2][8][4];
#pragma unroll
    for (int mt = 0; mt < 2; mt++)
#pragma unroll
        for (int nt = 0; nt < 8; nt++)
#pragma unroll
            for (int j = 0; j < 4; j++) acc[mt][nt][j] = 0.f;

    for (int k0 = 0; k0 < FDIM; k0 += 32) {
        // A tile: 128x32 -> fp16
#pragma unroll
        for (int t = 0; t < 4; t++) {
            int i = tid + t * 256;
            int r = i >> 3, c = (i & 7) << 2;
            float4 v = make_float4(0.f, 0.f, 0.f, 0.f);
            if (row0 + r < NN) v = *(const float4*)(X + (size_t)(row0 + r) * FDIM + k0 + c);
            *(__half2*)&su.ld.A[r][c]     = __floats2half2_rn(v.x, v.y);
            *(__half2*)&su.ld.A[r][c + 2] = __floats2half2_rn(v.z, v.w);
        }
        // B tile: 32(k)x128(n), stored transposed [n][k] as fp16
#pragma unroll
        for (int t = 0; t < 4; t++) {
            int i = tid + t * 256;
            int r = i & 31;             // k within chunk
            int c = (i >> 5) << 2;      // n
            float4 v = *(const float4*)(W + (size_t)(k0 + r) * H1DIM + c);
            su.ld.B[c + 0][r] = __float2half_rn(v.x);
            su.ld.B[c + 1][r] = __float2half_rn(v.y);
            su.ld.B[c + 2][r] = __float2half_rn(v.z);
            su.ld.B[c + 3][r] = __float2half_rn(v.w);
        }
        __syncthreads();
#pragma unroll
        for (int kk = 0; kk < 2; kk++) {
            const int ks = kk * 16;
            unsigned a[2][4], b[8][2];
#pragma unroll
            for (int mt = 0; mt < 2; mt++) {
                int rw = wm * 32 + mt * 16 + gid;
                a[mt][0] = *(const unsigned*)&su.ld.A[rw][ks + qid * 2];
                a[mt][1] = *(const unsigned*)&su.ld.A[rw + 8][ks + qid * 2];
                a[mt][2] = *(const unsigned*)&su.ld.A[rw][ks + 8 + qid * 2];
                a[mt][3] = *(const unsigned*)&su.ld.A[rw + 8][ks + 8 + qid * 2];
            }
#pragma unroll
            for (int nt = 0; nt < 8; nt++) {
                int cl = wn * 64 + nt * 8 + gid;
                b[nt][0] = *(const unsigned*)&su.ld.B[cl][ks + qid * 2];
                b[nt][1] = *(const unsigned*)&su.ld.B[cl][ks + 8 + qid * 2];
            }
#pragma unroll
            for (int mt = 0; mt < 2; mt++)
#pragma unroll
                for (int nt = 0; nt < 8; nt++) {
                    asm volatile(
                        "mma.sync.aligned.m16n8k16.row.col.f32.f16.f16.f32 "
                        "{%0,%1,%2,%3}, {%4,%5,%6,%7}, {%8,%9}, {%0,%1,%2,%3};\n"
                        : "+f"(acc[mt][nt][0]), "+f"(acc[mt][nt][1]),
                          "+f"(acc[mt][nt][2]), "+f"(acc[mt][nt][3])
                        : "r"(a[mt][0]), "r"(a[mt][1]), "r"(a[mt][2]), "r"(a[mt][3]),
                          "r"(b[nt][0]), "r"(b[nt][1]));
                }
        }
        __syncthreads();
    }
    // epilogue: store fp32 h to gmem + fp16 tile to smem stage
#pragma unroll
    for (int mt = 0; mt < 2; mt++) {
        int r0 = wm * 32 + mt * 16 + gid;
        int grw = row0 + r0;
#pragma unroll
        for (int nt = 0; nt < 8; nt++) {
            int cl = wn * 64 + nt * 8 + qid * 2;
            *(__half2*)&su.stage[r0][cl]     = __floats2half2_rn(acc[mt][nt][0], acc[mt][nt][1]);
            *(__half2*)&su.stage[r0 + 8][cl] = __floats2half2_rn(acc[mt][nt][2], acc[mt][nt][3]);
            if (grw < NN)
                *(float2*)(g_hp1 + (size_t)grw * H1DIM + cl) =
                    make_float2(acc[mt][nt][0], acc[mt][nt][1]);
            if (grw + 8 < NN)
                *(float2*)(g_hp1 + (size_t)(grw + 8) * H1DIM + cl) =
                    make_float2(acc[mt][nt][2], acc[mt][nt][3]);
        }
    }
    __syncthreads();
    // alpha epilogue: each warp computes logits for 16 rows of the tile
    {
        int head = lane >> 2, sub = lane & 3;
        float4 A4 = *(const float4*)(att_src + head * 16 + sub * 4);
        float4 D4 = *(const float4*)(att_dst + head * 16 + sub * 4);
#pragma unroll
        for (int rr = 0; rr < 16; rr++) {
            int r = warp * 16 + rr;
            int grow = row0 + r;
            if (grow >= NN) break;
            float2 f01 = __half22float2(*(__half2*)&su.stage[r][lane * 4]);
            float2 f23 = __half22float2(*(__half2*)&su.stage[r][lane * 4 + 2]);
            float s = f01.x * A4.x + f01.y * A4.y + f23.x * A4.z + f23.y * A4.w;
            float d = f01.x * D4.x + f01.y * D4.y + f23.x * D4.z + f23.y * D4.w;
            s += __shfl_xor_sync(0xffffffffu, s, 1);
            s += __shfl_xor_sync(0xffffffffu, s, 2);
            d += __shfl_xor_sync(0xffffffffu, d, 1);
            d += __shfl_xor_sync(0xffffffffu, d, 2);
            if (sub == 0) { g_as1[grow * 8 + head] = s; g_ad1[grow * 8 + head] = d; }
        }
    }
}

// ---------------------------------------------------------------------------
// agg1: bucket gather + softmax-normalize + bias + ELU. One warp per dst node.
// ---------------------------------------------------------------------------
__device__ __forceinline__ float edge_w1(int s, int head, float myad) {
    float t = __ldg(g_as1 + s * 8 + head) + myad;
    t = t > 0.f ? t : 0.2f * t;
    return __expf(t);
}

__global__ void __launch_bounds__(256) agg1_kernel(const float* __restrict__ b1) {
    int gw = (blockIdx.x * blockDim.x + threadIdx.x) >> 5;
    int lane = threadIdx.x & 31;
    if (gw >= NN) return;
    int head = lane >> 2;
    int beg = gw * CAP, end = beg + g_deg[gw];
    float myad = g_ad1[gw * 8 + head];
    float a0 = 0.f, a1 = 0.f, a2 = 0.f, a3 = 0.f, den = 0.f;
    int p = beg;
    for (; p + 4 <= end; p += 4) {
        int s0 = g_eidx[p], s1 = g_eidx[p + 1], s2 = g_eidx[p + 2], s3 = g_eidx[p + 3];
        float w0 = edge_w1(s0, head, myad);
        float w1 = edge_w1(s1, head, myad);
        float w2 = edge_w1(s2, head, myad);
        float w3 = edge_w1(s3, head, myad);
        float4 h0 = *(const float4*)(g_hp1 + (size_t)s0 * H1DIM + lane * 4);
        float4 h1 = *(const float4*)(g_hp1 + (size_t)s1 * H1DIM + lane * 4);
        float4 h2 = *(const float4*)(g_hp1 + (size_t)s2 * H1DIM + lane * 4);
        float4 h3 = *(const float4*)(g_hp1 + (size_t)s3 * H1DIM + lane * 4);
        den += (w0 + w1) + (w2 + w3);
        a0 += w0 * h0.x + w1 * h1.x + w2 * h2.x + w3 * h3.x;
        a1 += w0 * h0.y + w1 * h1.y + w2 * h2.y + w3 * h3.y;
        a2 += w0 * h0.z + w1 * h1.z + w2 * h2.z + w3 * h3.z;
        a3 += w0 * h0.w + w1 * h1.w + w2 * h2.w + w3 * h3.w;
    }
    for (; p < end; p++) {
        int s = g_eidx[p];
        float w = edge_w1(s, head, myad);
        float4 h = *(const float4*)(g_hp1 + (size_t)s * H1DIM + lane * 4);
        den += w;
        a0 += w * h.x; a1 += w * h.y; a2 += w * h.z; a3 += w * h.w;
    }
    float inv = __frcp_rn(den);
    const float* bb = b1 + lane * 4;
    float v0 = a0 * inv + bb[0];
    float v1 = a1 * inv + bb[1];
    float v2 = a2 * inv + bb[2];
    float v3 = a3 * inv + bb[3];
    v0 = v0 > 0.f ? v0 : __expf(v0) - 1.f;
    v1 = v1 > 0.f ? v1 : __expf(v1) - 1.f;
    v2 = v2 > 0.f ? v2 : __expf(v2) - 1.f;
    v3 = v3 > 0.f ? v3 : __expf(v3) - 1.f;
    *(float4*)(g_h1 + (size_t)gw * H1DIM + lane * 4) = make_float4(v0, v1, v2, v3);
}

// ---------------------------------------------------------------------------
// GEMM2 (fp16 MMA) + alpha2 fused: h2[N,16] = h1[N,128] @ W2[128,16].
// ---------------------------------------------------------------------------
__global__ void __launch_bounds__(256) gemm2_kernel(const float* __restrict__ W2,
                             const float* __restrict__ as2w, const float* __restrict__ ad2w) {
    __shared__ __align__(16) __half Hs[128][136];
    __shared__ __align__(16) __half Bt[16][136];
    const int tid = threadIdx.x;
    const int warp = tid >> 5, lane = tid & 31;
    const int gid = lane >> 2, qid = lane & 3;
    const int row0 = blockIdx.x * 128;

    // W2 -> Bt[n][k] fp16 (2048 elems, 8/thread)
#pragma unroll
    for (int t = 0; t < 8; t++) {
        int i = tid + t * 256;
        int k = i >> 4, c = i & 15;
        Bt[c][k] = __float2half_rn(W2[i]);
    }
    // h1 tile -> Hs fp16 (128 rows x 128, 16 float4 per thread)
#pragma unroll
    for (int t = 0; t < 16; t++) {
        int i = tid + t * 256;
        int r = i >> 5, c = (i & 31) << 2;
        float4 v = make_float4(0.f, 0.f, 0.f, 0.f);
        if (row0 + r < NN) v = *(const float4*)(g_h1 + (size_t)(row0 + r) * H1DIM + c);
        *(__half2*)&Hs[r][c]     = __floats2half2_rn(v.x, v.y);
        *(__half2*)&Hs[r][c + 2] = __floats2half2_rn(v.z, v.w);
    }
    __syncthreads();

    const int base = warp * 16;
    float acc[2][4];
#pragma unroll
    for (int nt = 0; nt < 2; nt++)
#pragma unroll
        for (int j = 0; j < 4; j++) acc[nt][j] = 0.f;

#pragma unroll
    for (int ks = 0; ks < H1DIM; ks += 16) {
        unsigned a[4], b[2][2];
        a[0] = *(const unsigned*)&Hs[base + gid][ks + qid * 2];
        a[1] = *(const unsigned*)&Hs[base + 8 + gid][ks + qid * 2];
        a[2] = *(const unsigned*)&Hs[base + gid][ks + 8 + qid * 2];
        a[3] = *(const unsigned*)&Hs[base + 8 + gid][ks + 8 + qid * 2];
#pragma unroll
        for (int nt = 0; nt < 2; nt++) {
            b[nt][0] = *(const unsigned*)&Bt[nt * 8 + gid][ks + qid * 2];
            b[nt][1] = *(const unsigned*)&Bt[nt * 8 + gid][ks + 8 + qid * 2];
        }
#pragma unroll
        for (int nt = 0; nt < 2; nt++) {
            asm volatile(
                "mma.sync.aligned.m16n8k16.row.col.f32.f16.f16.f32 "
                "{%0,%1,%2,%3}, {%4,%5,%6,%7}, {%8,%9}, {%0,%1,%2,%3};\n"
                : "+f"(acc[nt][0]), "+f"(acc[nt][1]), "+f"(acc[nt][2]), "+f"(acc[nt][3])
                : "r"(a[0]), "r"(a[1]), "r"(a[2]), "r"(a[3]),
                  "r"(b[nt][0]), "r"(b[nt][1]));
        }
    }
    // epilogue: rows r1 = row0+base+gid (c0,c1) and r2 = r1+8 (c2,c3)
    int r1 = row0 + base + gid, r2 = r1 + 8;
#pragma unroll
    for (int nt = 0; nt < 2; nt++) {
        int cl = nt * 8 + qid * 2;
        if (r1 < NN) *(float2*)(g_h2 + (size_t)r1 * CDIM2 + cl) = make_float2(acc[nt][0], acc[nt][1]);
        if (r2 < NN) *(float2*)(g_h2 + (size_t)r2 * CDIM2 + cl) = make_float2(acc[nt][2], acc[nt][3]);
    }
    // alpha2 logits: reduce over the 4 qid lanes holding each row's 16 cols
    float as_a = __ldg(as2w + qid * 2), as_b = __ldg(as2w + qid * 2 + 1);
    float as_c = __ldg(as2w + 8 + qid * 2), as_d = __ldg(as2w + 8 + qid * 2 + 1);
    float ad_a = __ldg(ad2w + qid * 2), ad_b = __ldg(ad2w + qid * 2 + 1);
    float ad_c = __ldg(ad2w + 8 + qid * 2), ad_d = __ldg(ad2w + 8 + qid * 2 + 1);
    float sv1 = acc[0][0] * as_a + acc[0][1] * as_b + acc[1][0] * as_c + acc[1][1] * as_d;
    float dv1 = acc[0][0] * ad_a + acc[0][1] * ad_b + acc[1][0] * ad_c + acc[1][1] * ad_d;
    float sv2 = acc[0][2] * as_a + acc[0][3] * as_b + acc[1][2] * as_c + acc[1][3] * as_d;
    float dv2 = acc[0][2] * ad_a + acc[0][3] * ad_b + acc[1][2] * ad_c + acc[1][3] * ad_d;
#pragma unroll
    for (int off = 1; off <= 2; off <<= 1) {
        sv1 += __shfl_xor_sync(0xffffffffu, sv1, off);
        dv1 += __shfl_xor_sync(0xffffffffu, dv1, off);
        sv2 += __shfl_xor_sync(0xffffffffu, sv2, off);
        dv2 += __shfl_xor_sync(0xffffffffu, dv2, off);
    }
    if (qid == 0) {
        if (r1 < NN) { g_as2[r1] = sv1; g_ad2[r1] = dv1; }
        if (r2 < NN) { g_as2[r2] = sv2; g_ad2[r2] = dv2; }
    }
}

// ---------------------------------------------------------------------------
// agg2: one warp per dst node; EIGHT 4-lane groups (8 edges in flight).
// den reduces exactly via butterfly (offsets mix only group bits).
// Tail: re-zero g_deg for the next replay.
// ---------------------------------------------------------------------------
__global__ void __launch_bounds__(256) agg2_kernel(const float* __restrict__ b2,
                                                   float* __restrict__ out) {
    int gw = (blockIdx.x * blockDim.x + threadIdx.x) >> 5;
    int lane = threadIdx.x & 31;
    if (gw >= NN) return;
    int beg = gw * CAP, end = beg + g_deg[gw];
    int grp = lane >> 2, sub = lane & 3;
    float ad = g_ad2[gw];
    float4 acc = make_float4(0.f, 0.f, 0.f, 0.f);
    float den = 0.f;
    for (int p = beg + grp; p < end; p += 8) {
        int s = g_eidx[p];
        float t = __ldg(g_as2 + s) + ad;
        t = t > 0.f ? t : 0.2f * t;
        float w = __expf(t);
        den += w;
        float4 h = *(const float4*)(g_h2 + (size_t)s * CDIM2 + sub * 4);
        acc.x += w * h.x; acc.y += w * h.y; acc.z += w * h.z; acc.w += w * h.w;
    }
#pragma unroll
    for (int off = 4; off <= 16; off <<= 1) {
        acc.x += __shfl_xor_sync(0xffffffffu, acc.x, off);
        acc.y += __shfl_xor_sync(0xffffffffu, acc.y, off);
        acc.z += __shfl_xor_sync(0xffffffffu, acc.z, off);
        acc.w += __shfl_xor_sync(0xffffffffu, acc.w, off);
        den   += __shfl_xor_sync(0xffffffffu, den, off);
    }
    if (lane < 4) {
        float inv = __frcp_rn(den);
        const float* bb = b2 + lane * 4;
        float4 r;
        r.x = acc.x * inv + bb[0];
        r.y = acc.y * inv + bb[1];
        r.z = acc.z * inv + bb[2];
        r.w = acc.w * inv + bb[3];
        *(float4*)(out + (size_t)gw * CDIM2 + lane * 4) = r;
    }
    if (lane == 0) g_deg[gw] = 0;   // reset for next graph replay
}

// ---------------------------------------------------------------------------
extern "C" void kernel_launch(void* const* d_in, const int* in_sizes, int n_in,
                              void* d_out, int out_size) {
    const float* x   = (const float*)d_in[0];
    const int*   ei  = (const int*)d_in[1];
    const float* W1  = (const float*)d_in[2];
    const float* as1 = (const float*)d_in[3];
    const float* ad1 = (const float*)d_in[4];
    const float* b1  = (const float*)d_in[5];
    const float* W2  = (const float*)d_in[6];
    const float* as2 = (const float*)d_in[7];
    const float* ad2 = (const float*)d_in[8];
    const float* b2  = (const float*)d_in[9];
    const int E = in_sizes[1] / 2;
    const int scat_threads = ((E + 3) >> 2) + NN;
    const int scat_blocks = (scat_threads + 255) / 256;

    phase1_kernel<<<G1BLOCKS + scat_blocks, 256>>>(x, W1, as1, ad1, ei, E);
    agg1_kernel<<<(NN * 32 + 255) / 256, 256>>>(b1);
    gemm2_kernel<<<(NN + 127) / 128, 256>>>(W2, as2, ad2);
    agg2_kernel<<<(NN * 32 + 255) / 256, 256>>>(b2, (float*)d_out);
}